// round 4
// baseline (speedup 1.0000x reference)
#include <cuda_runtime.h>
#include <cuda_bf16.h>
#include <cstdint>

constexpr int NPIX = 4096;
#define DEVI static __device__ __forceinline__

// bf16 scratch: q[B,N,32], k[B,N,32], v[B,N,256]
__device__ __nv_bfloat16 g_q[(size_t)4 * 4096 * 32];
__device__ __nv_bfloat16 g_k[(size_t)4 * 4096 * 32];
__device__ __nv_bfloat16 g_v[(size_t)4 * 4096 * 256];

DEVI uint32_t su(const void* p) { return (uint32_t)__cvta_generic_to_shared(p); }
DEVI void ldsm4(uint32_t& r0, uint32_t& r1, uint32_t& r2, uint32_t& r3, uint32_t a) {
    asm volatile("ldmatrix.sync.aligned.m8n8.x4.shared.b16 {%0,%1,%2,%3},[%4];"
                 : "=r"(r0), "=r"(r1), "=r"(r2), "=r"(r3) : "r"(a));
}
DEVI void ldsm4t(uint32_t& r0, uint32_t& r1, uint32_t& r2, uint32_t& r3, uint32_t a) {
    asm volatile("ldmatrix.sync.aligned.m8n8.x4.trans.shared.b16 {%0,%1,%2,%3},[%4];"
                 : "=r"(r0), "=r"(r1), "=r"(r2), "=r"(r3) : "r"(a));
}
DEVI void mma16816(float* c, const uint32_t* a, uint32_t b0, uint32_t b1) {
    asm volatile("mma.sync.aligned.m16n8k16.row.col.f32.bf16.bf16.f32 "
                 "{%0,%1,%2,%3},{%4,%5,%6,%7},{%8,%9},{%0,%1,%2,%3};"
                 : "+f"(c[0]), "+f"(c[1]), "+f"(c[2]), "+f"(c[3])
                 : "r"(a[0]), "r"(a[1]), "r"(a[2]), "r"(a[3]), "r"(b0), "r"(b1));
}
DEVI void cp16(uint32_t s, const void* g) {
    asm volatile("cp.async.cg.shared.global [%0],[%1],16;" ::"r"(s), "l"(g));
}
DEVI void cp_commit() { asm volatile("cp.async.commit_group;" ::: "memory"); }
template <int NN> DEVI void cp_wait() { asm volatile("cp.async.wait_group %0;" ::"n"(NN) : "memory"); }
DEVI float ex2f(float x) { float r; asm("ex2.approx.f32 %0,%1;" : "=f"(r) : "f"(x)); return r; }
DEVI uint32_t packbf2(float a, float b) {
    __nv_bfloat162 h = __floats2bfloat162_rn(a, b);
    return *reinterpret_cast<uint32_t*>(&h);
}

// ===========================================================================
// Projection: block = (m-tile 128, batch). v[128,256], q[128,32], k[128,32].
// smem: Xc[64][136], Ac[64][136], Wv[256][72], Wq[32][72], Wk[32][72] (bf16)
// ===========================================================================
constexpr int PROJ_SMEM = (64 * 136 * 2) * 2 + 256 * 72 * 2 + 32 * 72 * 2 * 2;

__global__ __launch_bounds__(256, 1) void proj_kernel(
    const float* __restrict__ ef, const float* __restrict__ sf, const float* __restrict__ attn,
    const float* __restrict__ Qw, const float* __restrict__ Qb,
    const float* __restrict__ Kw, const float* __restrict__ Kb,
    const float* __restrict__ Vw, const float* __restrict__ Vb)
{
    extern __shared__ __align__(16) char smem_raw[];
    __nv_bfloat16* Xc = (__nv_bfloat16*)smem_raw;
    __nv_bfloat16* Ac = Xc + 64 * 136;
    __nv_bfloat16* Wv = Ac + 64 * 136;
    __nv_bfloat16* Wq = Wv + 256 * 72;
    __nv_bfloat16* Wk = Wq + 32 * 72;

    const int b = blockIdx.y, m0 = blockIdx.x * 128;
    const int tid = threadIdx.x, lane = tid & 31, warp = tid >> 5, mw = warp * 16;

    float ov[128], oq[16], ok[16];
#pragma unroll
    for (int i = 0; i < 128; i++) ov[i] = 0.f;
#pragma unroll
    for (int i = 0; i < 16; i++) { oq[i] = 0.f; ok[i] = 0.f; }

#pragma unroll 1
    for (int ic = 0; ic < 8; ic++) {
        const int i0 = ic * 64;
        __syncthreads();
#pragma unroll
        for (int t = 0; t < 8; t++) {   // X chunk [64 i][128 m]
            int idx = tid + t * 256, il = idx >> 5, j = (idx & 31) * 4;
            int gi = i0 + il;
            const float* src = (gi < 256) ? (ef + ((size_t)(b * 256 + gi)) * NPIX + m0 + j)
                                          : (sf + ((size_t)(b * 256 + gi - 256)) * NPIX + m0 + j);
            float4 v = *(const float4*)src;
            *(uint2*)(Xc + il * 136 + j) = make_uint2(packbf2(v.x, v.y), packbf2(v.z, v.w));
        }
        if (ic < 4) {
#pragma unroll
            for (int t = 0; t < 8; t++) {
                int idx = tid + t * 256, il = idx >> 5, j = (idx & 31) * 4;
                float4 v = *(const float4*)(attn + ((size_t)(b * 256 + i0 + il)) * NPIX + m0 + j);
                *(uint2*)(Ac + il * 136 + j) = make_uint2(packbf2(v.x, v.y), packbf2(v.z, v.w));
            }
            for (int t = tid; t < 32 * 16; t += 256) {
                int r = t >> 4, j = (t & 15) * 4;
                float4 v = *(const float4*)(Kw + (size_t)r * 256 + i0 + j);
                *(uint2*)(Wk + r * 72 + j) = make_uint2(packbf2(v.x, v.y), packbf2(v.z, v.w));
            }
        }
#pragma unroll
        for (int t = 0; t < 16; t++) {
            int idx = tid + t * 256, r = idx >> 4, j = (idx & 15) * 4;
            float4 v = *(const float4*)(Vw + (size_t)r * 512 + i0 + j);
            *(uint2*)(Wv + r * 72 + j) = make_uint2(packbf2(v.x, v.y), packbf2(v.z, v.w));
        }
        for (int t = tid; t < 32 * 16; t += 256) {
            int r = t >> 4, j = (t & 15) * 4;
            float4 v = *(const float4*)(Qw + (size_t)r * 512 + i0 + j);
            *(uint2*)(Wq + r * 72 + j) = make_uint2(packbf2(v.x, v.y), packbf2(v.z, v.w));
        }
        __syncthreads();

#pragma unroll
        for (int kt = 0; kt < 4; kt++) {
            const int k0 = kt * 16;
            uint32_t xa[4];
            ldsm4t(xa[0], xa[1], xa[2], xa[3],
                su(Xc + (k0 + (lane & 7) + ((lane >> 4) << 3)) * 136 + mw + (((lane >> 3) & 1) << 3)));
#pragma unroll
            for (int cp = 0; cp < 16; cp++) {
                uint32_t b0, b1, b2, b3;
                ldsm4(b0, b1, b2, b3, su(Wv + ((cp << 4) + (lane & 15)) * 72 + k0 + ((lane >> 4) << 3)));
                mma16816(ov + cp * 8, xa, b0, b2);
                mma16816(ov + cp * 8 + 4, xa, b1, b3);
            }
            {
                uint32_t b0, b1, b2, b3;
                ldsm4(b0, b1, b2, b3, su(Wq + (lane & 15) * 72 + k0 + ((lane >> 4) << 3)));
                mma16816(oq + 0, xa, b0, b2);
                mma16816(oq + 4, xa, b1, b3);
                ldsm4(b0, b1, b2, b3, su(Wq + (16 + (lane & 15)) * 72 + k0 + ((lane >> 4) << 3)));
                mma16816(oq + 8, xa, b0, b2);
                mma16816(oq + 12, xa, b1, b3);
            }
            if (ic < 4) {
                uint32_t aa[4];
                ldsm4t(aa[0], aa[1], aa[2], aa[3],
                    su(Ac + (k0 + (lane & 7) + ((lane >> 4) << 3)) * 136 + mw + (((lane >> 3) & 1) << 3)));
                uint32_t b0, b1, b2, b3;
                ldsm4(b0, b1, b2, b3, su(Wk + (lane & 15) * 72 + k0 + ((lane >> 4) << 3)));
                mma16816(ok + 0, aa, b0, b2);
                mma16816(ok + 4, aa, b1, b3);
                ldsm4(b0, b1, b2, b3, su(Wk + (16 + (lane & 15)) * 72 + k0 + ((lane >> 4) << 3)));
                mma16816(ok + 8, aa, b0, b2);
                mma16816(ok + 12, aa, b1, b3);
            }
        }
    }

    const int r0 = m0 + mw + (lane >> 2), cb = (lane & 3) * 2;
#pragma unroll
    for (int ct = 0; ct < 32; ct++) {
        int c = ct * 8 + cb;
        float bb0 = Vb[c], bb1 = Vb[c + 1];
        *(uint32_t*)&g_v[((size_t)(b * NPIX + r0)) * 256 + c]     = packbf2(ov[ct * 4 + 0] + bb0, ov[ct * 4 + 1] + bb1);
        *(uint32_t*)&g_v[((size_t)(b * NPIX + r0 + 8)) * 256 + c] = packbf2(ov[ct * 4 + 2] + bb0, ov[ct * 4 + 3] + bb1);
    }
#pragma unroll
    for (int dt = 0; dt < 4; dt++) {
        int d = dt * 8 + cb;
        float bq0 = Qb[d], bq1 = Qb[d + 1];
        *(uint32_t*)&g_q[((size_t)(b * NPIX + r0)) * 32 + d]     = packbf2(oq[dt * 4 + 0] + bq0, oq[dt * 4 + 1] + bq1);
        *(uint32_t*)&g_q[((size_t)(b * NPIX + r0 + 8)) * 32 + d] = packbf2(oq[dt * 4 + 2] + bq0, oq[dt * 4 + 3] + bq1);
        float bk0 = Kb[d], bk1 = Kb[d + 1];
        *(uint32_t*)&g_k[((size_t)(b * NPIX + r0)) * 32 + d]     = packbf2(ok[dt * 4 + 0] + bk0, ok[dt * 4 + 1] + bk1);
        *(uint32_t*)&g_k[((size_t)(b * NPIX + r0 + 8)) * 32 + d] = packbf2(ok[dt * 4 + 2] + bk0, ok[dt * 4 + 3] + bk1);
    }
}

// ===========================================================================
// Flash attention: block = (m-tile 128, batch); warp owns 16 rows x 256 ch.
// smem: Qs[128][40], Ks[2][64][40], Vs[2][64][264] bf16.
// ===========================================================================
constexpr int FLASH_SMEM = 128 * 40 * 2 + 2 * 64 * 40 * 2 + 2 * 64 * 264 * 2;

__global__ __launch_bounds__(256, 1) void flash_kernel(
    const float* __restrict__ ef, const float* __restrict__ gamma_p, float* __restrict__ out)
{
    extern __shared__ __align__(16) char smem_raw[];
    __nv_bfloat16* Qs = (__nv_bfloat16*)smem_raw;
    __nv_bfloat16* Ks = Qs + 128 * 40;
    __nv_bfloat16* Vs = Ks + 2 * 64 * 40;

    const int b = blockIdx.y, m0 = blockIdx.x * 128;
    const int tid = threadIdx.x, lane = tid & 31, warp = tid >> 5, mw = warp * 16;
    const float LOG2E = 1.4426950408889634f;

    const __nv_bfloat16* gq = g_q + (size_t)b * NPIX * 32;
    const __nv_bfloat16* gk = g_k + (size_t)b * NPIX * 32;
    const __nv_bfloat16* gv = g_v + (size_t)b * NPIX * 256;

#pragma unroll
    for (int t = 0; t < 2; t++) {
        int idx = tid + t * 256, r = idx >> 2, seg = idx & 3;
        cp16(su(Qs + r * 40 + seg * 8), gq + (size_t)(m0 + r) * 32 + seg * 8);
    }
    auto load_kv = [&](int nt, int buf) {
        int n0 = nt * 64;
        { int r = tid >> 2, seg = tid & 3;
          cp16(su(Ks + buf * 64 * 40 + r * 40 + seg * 8), gk + (size_t)(n0 + r) * 32 + seg * 8); }
#pragma unroll
        for (int t = 0; t < 8; t++) {
            int idx = tid + t * 256, r = idx >> 5, seg = idx & 31;
            cp16(su(Vs + buf * 64 * 264 + r * 264 + seg * 8), gv + (size_t)(n0 + r) * 256 + seg * 8);
        }
    };
    load_kv(0, 0);
    cp_commit();

    float o[128];
#pragma unroll
    for (int i = 0; i < 128; i++) o[i] = 0.f;
    float m0r = -1e30f, m1r = -1e30f, l0r = 0.f, l1r = 0.f;
    uint32_t qa[2][4];

#pragma unroll 1
    for (int nt = 0; nt < 64; nt++) {
        const int buf = nt & 1;
        if (nt + 1 < 64) { load_kv(nt + 1, buf ^ 1); cp_commit(); cp_wait<1>(); }
        else             { cp_wait<0>(); }
        __syncthreads();
        if (nt == 0) {
#pragma unroll
            for (int kt = 0; kt < 2; kt++)
                ldsm4(qa[kt][0], qa[kt][1], qa[kt][2], qa[kt][3],
                    su(Qs + (mw + (lane & 15)) * 40 + kt * 16 + ((lane >> 4) << 3)));
        }
        // S = Q K^T  [16m x 64n]
        float s[8][4];
#pragma unroll
        for (int j = 0; j < 8; j++) { s[j][0] = s[j][1] = s[j][2] = s[j][3] = 0.f; }
        __nv_bfloat16* Kb_ = Ks + buf * 64 * 40;
#pragma unroll
        for (int jp = 0; jp < 4; jp++)
#pragma unroll
            for (int kt = 0; kt < 2; kt++) {
                uint32_t r0, r1, r2, r3;
                ldsm4(r0, r1, r2, r3,
                    su(Kb_ + (jp * 16 + (lane & 15)) * 40 + kt * 16 + ((lane >> 4) << 3)));
                mma16816(s[jp * 2],     qa[kt], r0, r2);
                mma16816(s[jp * 2 + 1], qa[kt], r1, r3);
            }
        // online softmax (rows r0=lane>>2, r1=r0+8; quad holds 8 cols/tile)
        float tm0 = -1e30f, tm1 = -1e30f;
#pragma unroll
        for (int j = 0; j < 8; j++) {
            tm0 = fmaxf(tm0, fmaxf(s[j][0], s[j][1]));
            tm1 = fmaxf(tm1, fmaxf(s[j][2], s[j][3]));
        }
        tm0 = fmaxf(tm0, __shfl_xor_sync(~0u, tm0, 1)); tm0 = fmaxf(tm0, __shfl_xor_sync(~0u, tm0, 2));
        tm1 = fmaxf(tm1, __shfl_xor_sync(~0u, tm1, 1)); tm1 = fmaxf(tm1, __shfl_xor_sync(~0u, tm1, 2));
        float mn0 = fmaxf(m0r, tm0), mn1 = fmaxf(m1r, tm1);
        float sc0 = ex2f((m0r - mn0) * LOG2E), sc1 = ex2f((m1r - mn1) * LOG2E);
        m0r = mn0; m1r = mn1;
        float ts0 = 0.f, ts1 = 0.f;
#pragma unroll
        for (int j = 0; j < 8; j++) {
            s[j][0] = ex2f((s[j][0] - mn0) * LOG2E); s[j][1] = ex2f((s[j][1] - mn0) * LOG2E);
            s[j][2] = ex2f((s[j][2] - mn1) * LOG2E); s[j][3] = ex2f((s[j][3] - mn1) * LOG2E);
            ts0 += s[j][0] + s[j][1]; ts1 += s[j][2] + s[j][3];
        }
        ts0 += __shfl_xor_sync(~0u, ts0, 1); ts0 += __shfl_xor_sync(~0u, ts0, 2);
        ts1 += __shfl_xor_sync(~0u, ts1, 1); ts1 += __shfl_xor_sync(~0u, ts1, 2);
        l0r = l0r * sc0 + ts0; l1r = l1r * sc1 + ts1;
#pragma unroll
        for (int ct = 0; ct < 32; ct++) {
            o[ct * 4 + 0] *= sc0; o[ct * 4 + 1] *= sc0;
            o[ct * 4 + 2] *= sc1; o[ct * 4 + 3] *= sc1;
        }
        uint32_t pa[4][4];
#pragma unroll
        for (int kt = 0; kt < 4; kt++) {
            pa[kt][0] = packbf2(s[2 * kt][0], s[2 * kt][1]);
            pa[kt][1] = packbf2(s[2 * kt][2], s[2 * kt][3]);
            pa[kt][2] = packbf2(s[2 * kt + 1][0], s[2 * kt + 1][1]);
            pa[kt][3] = packbf2(s[2 * kt + 1][2], s[2 * kt + 1][3]);
        }
        // O += P V
        __nv_bfloat16* Vb_ = Vs + buf * 64 * 264;
#pragma unroll
        for (int kt = 0; kt < 4; kt++)
#pragma unroll
            for (int cp = 0; cp < 16; cp++) {
                uint32_t r0, r1, r2, r3;
                ldsm4t(r0, r1, r2, r3,
                    su(Vb_ + (kt * 16 + (lane & 15)) * 264 + cp * 16 + ((lane >> 4) << 3)));
                mma16816(o + cp * 8,     pa[kt], r0, r1);
                mma16816(o + cp * 8 + 4, pa[kt], r2, r3);
            }
        __syncthreads();
    }

    const float gm = gamma_p[0];
    const float inv0 = gm / l0r, inv1 = gm / l1r;
    const int mr0 = m0 + mw + (lane >> 2), cb = (lane & 3) * 2;
#pragma unroll
    for (int ct = 0; ct < 32; ct++) {
        int c = ct * 8 + cb;
        size_t i00 = ((size_t)(b * 256 + c)) * NPIX + mr0;
        size_t i01 = ((size_t)(b * 256 + c + 1)) * NPIX + mr0;
        out[i00]     = o[ct * 4 + 0] * inv0 + ef[i00];
        out[i01]     = o[ct * 4 + 1] * inv0 + ef[i01];
        out[i00 + 8] = o[ct * 4 + 2] * inv1 + ef[i00 + 8];
        out[i01 + 8] = o[ct * 4 + 3] * inv1 + ef[i01 + 8];
    }
}

extern "C" void kernel_launch(void* const* d_in, const int* in_sizes, int n_in,
                              void* d_out, int out_size) {
    const float* ef = (const float*)d_in[0];
    const float* sf = (const float*)d_in[1];
    const float* At = (const float*)d_in[2];
    const float* Qw = (const float*)d_in[3];
    const float* Qb = (const float*)d_in[4];
    const float* Kw = (const float*)d_in[5];
    const float* Kb = (const float*)d_in[6];
    const float* Vw = (const float*)d_in[7];
    const float* Vb = (const float*)d_in[8];
    const float* gm = (const float*)d_in[9];
    float* out = (float*)d_out;

    cudaFuncSetAttribute(proj_kernel, cudaFuncAttributeMaxDynamicSharedMemorySize, PROJ_SMEM);
    cudaFuncSetAttribute(flash_kernel, cudaFuncAttributeMaxDynamicSharedMemorySize, FLASH_SMEM);

    proj_kernel<<<dim3(32, 4), 256, PROJ_SMEM>>>(ef, sf, At, Qw, Qb, Kw, Kb, Vw, Vb);
    flash_kernel<<<dim3(32, 4), 256, FLASH_SMEM>>>(ef, gm, out);
}